// round 6
// baseline (speedup 1.0000x reference)
#include <cuda_runtime.h>
#include <cuda_fp16.h>

#define NN 100000
#define EE 1600000
#define FIN 100
#define D 64
#define GG 500
#define SCAN_T 512
#define SCAN_NB ((NN + SCAN_T - 1) / SCAN_T)

// ---------------- scratch (device globals; no allocs allowed) ----------------
__device__ float g_deg[NN];
__device__ int   g_cntn[NN];
__device__ int   g_ptr[NN + 1];
__device__ int   g_partials[SCAN_NB];
__device__ int2  g_csr[EE];        // packed {row, norm_bits}
__device__ float g_out0[NN * D];
__device__ uint4 g_hh[NN * 8];     // h in fp16: 64 halves = 8 uint4 per row
__device__ float g_aggA[NN * D];
__device__ float g_aggB[NN * D];
__device__ float g_sums[GG * D];
__device__ float g_cnt[GG];
__device__ int g_is64_edge;
__device__ int g_is64_batch;

__device__ __forceinline__ int load_idx(const void* p, long long i, int is64) {
    return is64 ? (int)((const long long*)p)[i] : ((const int*)p)[i];
}

// ptr fixup inlined (scan3 eliminated): final ptr(n) = g_ptr[n] + partials[n>>9]
__device__ __forceinline__ int ptr_of(int n) {
    return (n == NN) ? EE : g_ptr[n] + g_partials[n >> 9];
}

// Detect int64 vs int32 index arrays (odd 32-bit words all zero => int64).
__global__ void detect_kernel(const int* ei, const int* bat) {
    int i = threadIdx.x;  // 32 threads
    int nz_e = 0, nz_b = 0;
    for (int j = i; j < 128; j += 32) {
        int w = 1 + 700 * j;  // always odd, < NN words
        nz_e |= (ei[w] != 0);
        nz_b |= (bat[w] != 0);
    }
    unsigned be = __ballot_sync(0xffffffffu, nz_e);
    unsigned bb = __ballot_sync(0xffffffffu, nz_b);
    if (i == 0) {
        g_is64_edge = (be == 0);
        g_is64_batch = (bb == 0);
    }
}

// ---------------- fused: lin0 GEMM (fp32) + degree/count histogram -----------
#define K0 FIN
#define KB0 20
#define APAD 132
__global__ void fused_lin0_deg(const float* __restrict__ A, const float* __restrict__ W,
                               const float* __restrict__ biasC, float* __restrict__ C,
                               const void* ei, const float* __restrict__ ew,
                               int gemm_blocks) {
    __shared__ float Ws[K0 * D];
    __shared__ float As[KB0 * APAD];
    int tid = threadIdx.x;

    if (blockIdx.x >= gemm_blocks) {
        int e = (blockIdx.x - gemm_blocks) * 256 + tid;
        if (e < EE) {
            int c = load_idx(ei, (long long)EE + e, g_is64_edge);
            atomicAdd(&g_deg[c], ew[e]);
            atomicAdd(&g_cntn[c], 1);
        }
        return;
    }

    int row0 = blockIdx.x * 128;
    for (int i = tid; i < K0 * D; i += 256) Ws[i] = W[i];
    int tx = tid & 15, ty = tid >> 4;
    float acc[8][4] = {};

    for (int kb = 0; kb < K0; kb += KB0) {
        __syncthreads();
        for (int i = tid; i < 128 * KB0; i += 256) {
            int rr = i / KB0, kk = i - rr * KB0;
            int r = row0 + rr;
            As[kk * APAD + rr] = (r < NN) ? A[(long long)r * K0 + kb + kk] : 0.f;
        }
        __syncthreads();
#pragma unroll
        for (int k = 0; k < KB0; k++) {
            float4 a0 = *(const float4*)&As[k * APAD + ty * 8];
            float4 a1 = *(const float4*)&As[k * APAD + ty * 8 + 4];
            float4 wv = *(const float4*)&Ws[(kb + k) * D + tx * 4];
            float av[8] = {a0.x, a0.y, a0.z, a0.w, a1.x, a1.y, a1.z, a1.w};
#pragma unroll
            for (int i2 = 0; i2 < 8; i2++) {
                acc[i2][0] += av[i2] * wv.x;
                acc[i2][1] += av[i2] * wv.y;
                acc[i2][2] += av[i2] * wv.z;
                acc[i2][3] += av[i2] * wv.w;
            }
        }
    }
    int c0 = tx * 4;
    float4 bc = *(const float4*)&biasC[c0];
#pragma unroll
    for (int i2 = 0; i2 < 8; i2++) {
        int r = row0 + ty * 8 + i2;
        if (r >= NN) break;
        float4 v = make_float4(fmaxf(acc[i2][0] + bc.x, 0.f), fmaxf(acc[i2][1] + bc.y, 0.f),
                               fmaxf(acc[i2][2] + bc.z, 0.f), fmaxf(acc[i2][3] + bc.w, 0.f));
        *(float4*)&C[(long long)r * D + c0] = v;
    }
}

// ---------------- two-level exclusive scan over g_cntn -> g_ptr --------------
__global__ void scan1_kernel() {
    __shared__ int sh[SCAN_T];
    int tid = threadIdx.x;
    int i = blockIdx.x * SCAN_T + tid;
    int v = (i < NN) ? g_cntn[i] : 0;
    sh[tid] = v;
    __syncthreads();
    for (int off = 1; off < SCAN_T; off <<= 1) {
        int t = (tid >= off) ? sh[tid - off] : 0;
        __syncthreads();
        sh[tid] += t;
        __syncthreads();
    }
    if (i < NN) g_ptr[i] = sh[tid] - v;  // exclusive (local)
    if (tid == SCAN_T - 1) g_partials[blockIdx.x] = sh[tid];
}

__global__ void scan2_kernel() {  // 1 block of 256 (SCAN_NB=196 < 256)
    __shared__ int sh[256];
    int tid = threadIdx.x;
    int v = (tid < SCAN_NB) ? g_partials[tid] : 0;
    sh[tid] = v;
    __syncthreads();
    for (int off = 1; off < 256; off <<= 1) {
        int t = (tid >= off) ? sh[tid - off] : 0;
        __syncthreads();
        sh[tid] += t;
        __syncthreads();
    }
    if (tid < SCAN_NB) g_partials[tid] = sh[tid] - v;  // exclusive
}

// ---------------- scatter edges into packed CSR, norm inline -----------------
__global__ void scatter_kernel(const void* ei, const float* __restrict__ w) {
    int e = blockIdx.x * blockDim.x + threadIdx.x;
    if (e >= EE) return;
    int is64 = g_is64_edge;
    int r = load_idx(ei, e, is64);
    int c = load_idx(ei, (long long)EE + e, is64);
    float dr = g_deg[r], dc = g_deg[c];
    float ir = dr > 0.f ? rsqrtf(dr) : 0.f;
    float ic = dc > 0.f ? rsqrtf(dc) : 0.f;
    int old = atomicSub(&g_cntn[c], 1);
    int p = ptr_of(c) + old - 1;
    float nv = ir * w[e] * ic;
    g_csr[p] = make_int2(r, __float_as_int(nv));
}

// ---------------- 3xTF32 tensor-core GEMM: h[fp16] = A[N,64] @ W[64,64] ------
// Error-compensated tf32: C = Ah*Bh + Ah*Bl + Al*Bh  (~fp32 accuracy).
// 256 threads = 8 warps; warp computes 16 rows x 64 cols via m16n8k8 mma.
#define WPAD 65
__device__ __forceinline__ unsigned cvt_tf32(float f) {
    unsigned t;
    asm("cvt.rna.tf32.f32 %0, %1;" : "=r"(t) : "f"(f));
    return t;
}

__global__ void gemm_tf32x3(const float* __restrict__ A, const float* __restrict__ W,
                            unsigned* __restrict__ hout, int nrows) {
    __shared__ unsigned WsH[D * WPAD];
    __shared__ unsigned WsL[D * WPAD];
    int tid = threadIdx.x;
    for (int i = tid; i < D * D; i += 256) {
        int k = i >> 6, n = i & 63;
        float f = W[i];
        unsigned hi = cvt_tf32(f);
        float res = f - __uint_as_float(hi);
        WsH[k * WPAD + n] = hi;
        WsL[k * WPAD + n] = cvt_tf32(res);
    }
    __syncthreads();

    int warp = tid >> 5, lane = tid & 31;
    int rbase = blockIdx.x * 128 + warp * 16;
    int rlo = rbase + (lane >> 2);
    int rhi = rlo + 8;
    int kc = lane & 3;

    float acc[8][4] = {};
#pragma unroll
    for (int ks = 0; ks < 8; ks++) {
        int k0 = ks * 8;
        float fa[4];
        fa[0] = (rlo < nrows) ? A[(long long)rlo * D + k0 + kc]     : 0.f;
        fa[1] = (rhi < nrows) ? A[(long long)rhi * D + k0 + kc]     : 0.f;
        fa[2] = (rlo < nrows) ? A[(long long)rlo * D + k0 + kc + 4] : 0.f;
        fa[3] = (rhi < nrows) ? A[(long long)rhi * D + k0 + kc + 4] : 0.f;
        unsigned ah[4], al[4];
#pragma unroll
        for (int j = 0; j < 4; j++) {
            ah[j] = cvt_tf32(fa[j]);
            al[j] = cvt_tf32(fa[j] - __uint_as_float(ah[j]));
        }
#pragma unroll
        for (int t = 0; t < 8; t++) {
            int n0 = t * 8;
            int bi0 = (k0 + kc) * WPAD + n0 + (lane >> 2);
            int bi1 = (k0 + kc + 4) * WPAD + n0 + (lane >> 2);
            unsigned bh0 = WsH[bi0], bh1 = WsH[bi1];
            unsigned bl0 = WsL[bi0], bl1 = WsL[bi1];
            asm volatile(
                "mma.sync.aligned.m16n8k8.row.col.f32.tf32.tf32.f32 "
                "{%0,%1,%2,%3}, {%4,%5,%6,%7}, {%8,%9}, {%0,%1,%2,%3};"
                : "+f"(acc[t][0]), "+f"(acc[t][1]), "+f"(acc[t][2]), "+f"(acc[t][3])
                : "r"(al[0]), "r"(al[1]), "r"(al[2]), "r"(al[3]), "r"(bh0), "r"(bh1));
            asm volatile(
                "mma.sync.aligned.m16n8k8.row.col.f32.tf32.tf32.f32 "
                "{%0,%1,%2,%3}, {%4,%5,%6,%7}, {%8,%9}, {%0,%1,%2,%3};"
                : "+f"(acc[t][0]), "+f"(acc[t][1]), "+f"(acc[t][2]), "+f"(acc[t][3])
                : "r"(ah[0]), "r"(ah[1]), "r"(ah[2]), "r"(ah[3]), "r"(bl0), "r"(bl1));
            asm volatile(
                "mma.sync.aligned.m16n8k8.row.col.f32.tf32.tf32.f32 "
                "{%0,%1,%2,%3}, {%4,%5,%6,%7}, {%8,%9}, {%0,%1,%2,%3};"
                : "+f"(acc[t][0]), "+f"(acc[t][1]), "+f"(acc[t][2]), "+f"(acc[t][3])
                : "r"(ah[0]), "r"(ah[1]), "r"(ah[2]), "r"(ah[3]), "r"(bh0), "r"(bh1));
        }
    }

    // epilogue: pack fp16 pairs; rows (lane>>2) and +8; cols 2*(t*4+kc)
#pragma unroll
    for (int t = 0; t < 8; t++) {
        int ci = t * 4 + kc;  // u32 col index within 32-wide row
        if (rlo < nrows) {
            __half2 h = __floats2half2_rn(acc[t][0], acc[t][1]);
            hout[(long long)rlo * 32 + ci] = *(unsigned*)&h;
        }
        if (rhi < nrows) {
            __half2 h = __floats2half2_rn(acc[t][2], acc[t][3]);
            hout[(long long)rhi * 32 + ci] = *(unsigned*)&h;
        }
    }
}

// ---------------- CSR aggregation (fp16 gather, packed csr) ------------------
__device__ __forceinline__ void agg_core(int node, const uint4* __restrict__ h,
                                         int q, int p, float acc[8]) {
    int s = ptr_of(node), e = ptr_of(node + 1);
    for (int i = s + q; i < e; i += 4) {
        int2 ed = g_csr[i];
        float nv = __int_as_float(ed.y);
        uint4 u = h[ed.x * 8 + p];
        __half2* hh = (__half2*)&u;
#pragma unroll
        for (int c = 0; c < 4; c++) {
            float2 f = __half22float2(hh[c]);
            acc[2 * c]     += f.x * nv;
            acc[2 * c + 1] += f.y * nv;
        }
    }
#pragma unroll
    for (int c = 0; c < 8; c++) {
        acc[c] += __shfl_xor_sync(0xffffffffu, acc[c], 8);
        acc[c] += __shfl_xor_sync(0xffffffffu, acc[c], 16);
    }
}

__global__ void agg_half(const uint4* __restrict__ h,
                         const float* __restrict__ bias, float* __restrict__ outp) {
    int node = (blockIdx.x * blockDim.x + threadIdx.x) >> 5;
    if (node >= NN) return;
    int lane = threadIdx.x & 31;
    int q = lane >> 3, p = lane & 7;
    float acc[8] = {};
    agg_core(node, h, q, p, acc);
    if (q == 0) {
        float4 b0 = *(const float4*)&bias[8 * p];
        float4 b1 = *(const float4*)&bias[8 * p + 4];
        float4 o0 = make_float4(fmaxf(acc[0] + b0.x, 0.f), fmaxf(acc[1] + b0.y, 0.f),
                                fmaxf(acc[2] + b0.z, 0.f), fmaxf(acc[3] + b0.w, 0.f));
        float4 o1 = make_float4(fmaxf(acc[4] + b1.x, 0.f), fmaxf(acc[5] + b1.y, 0.f),
                                fmaxf(acc[6] + b1.z, 0.f), fmaxf(acc[7] + b1.w, 0.f));
        float* row = outp + (long long)node * D + 8 * p;
        *(float4*)row = o0;
        *(float4*)(row + 4) = o1;
    }
}

__device__ __forceinline__ void red_add_v4(float4* addr, float4 v) {
    asm volatile("red.global.add.v4.f32 [%0], {%1,%2,%3,%4};"
                 :: "l"(addr), "f"(v.x), "f"(v.y), "f"(v.z), "f"(v.w)
                 : "memory");
}

// Last layer: aggregate + bias + relu + mean-pool accumulate.
__global__ void agg_pool(const uint4* __restrict__ h,
                         const float* __restrict__ bias, const void* batch) {
    int node = (blockIdx.x * blockDim.x + threadIdx.x) >> 5;
    if (node >= NN) return;
    int lane = threadIdx.x & 31;
    int q = lane >> 3, p = lane & 7;
    float acc[8] = {};
    agg_core(node, h, q, p, acc);
    if (q == 0) {
        int g = load_idx(batch, node, g_is64_batch);
        float4 b0 = *(const float4*)&bias[8 * p];
        float4 b1 = *(const float4*)&bias[8 * p + 4];
        float4 o0 = make_float4(fmaxf(acc[0] + b0.x, 0.f), fmaxf(acc[1] + b0.y, 0.f),
                                fmaxf(acc[2] + b0.z, 0.f), fmaxf(acc[3] + b0.w, 0.f));
        float4 o1 = make_float4(fmaxf(acc[4] + b1.x, 0.f), fmaxf(acc[5] + b1.y, 0.f),
                                fmaxf(acc[6] + b1.z, 0.f), fmaxf(acc[7] + b1.w, 0.f));
        float* row = g_sums + g * D + 8 * p;
        red_add_v4((float4*)row, o0);
        red_add_v4((float4*)(row + 4), o1);
        if (p == 0) atomicAdd(&g_cnt[g], 1.0f);
    }
}

// ---------------- fused MLP tail: lin1 -> fc0 -> fc1 -> lin2 ----------------
__global__ void tail_kernel(const float* __restrict__ W1, const float* __restrict__ b1,
                            const float* __restrict__ fcw, const float* __restrict__ fcb,
                            const float* __restrict__ w2, const float* __restrict__ b2,
                            float* __restrict__ out) {
    int g = blockIdx.x, tid = threadIdx.x;  // 64 threads
    __shared__ float buf[2][64];
    __shared__ float red[64];

    buf[0][tid] = g_sums[g * D + tid] / fmaxf(g_cnt[g], 1.f);
    __syncthreads();
    {
        float acc = 0.f;
#pragma unroll
        for (int k = 0; k < 64; k++) acc += buf[0][k] * W1[k * D + tid];
        buf[1][tid] = fmaxf(acc + b1[tid], 0.f);
        __syncthreads();
    }
    int cur = 1;
    for (int L = 0; L < 2; L++) {
        const float* W = fcw + L * D * D;
        float acc = 0.f;
#pragma unroll
        for (int k = 0; k < 64; k++) acc += buf[cur][k] * W[k * D + tid];
        __syncthreads();
        buf[cur ^ 1][tid] = fmaxf(acc + fcb[L * D + tid], 0.f);
        cur ^= 1;
        __syncthreads();
    }
    red[tid] = buf[cur][tid] * w2[tid];
    __syncthreads();
    if (tid < 32) {
        float s = red[tid] + red[tid + 32];
#pragma unroll
        for (int off = 16; off; off >>= 1) s += __shfl_down_sync(0xffffffffu, s, off);
        if (tid == 0) out[g] = s + b2[0];
    }
}

// ---------------- launch ----------------
extern "C" void kernel_launch(void* const* d_in, const int* in_sizes, int n_in,
                              void* d_out, int out_size) {
    const float* x      = (const float*)d_in[0];
    const void*  ei     = d_in[1];
    const float* ew     = (const float*)d_in[2];
    const void*  batch  = d_in[3];
    const float* lin0_w = (const float*)d_in[4];
    const float* lin0_b = (const float*)d_in[5];
    const float* conv_w = (const float*)d_in[6];
    const float* conv_b = (const float*)d_in[7];
    const float* lin1_w = (const float*)d_in[8];
    const float* lin1_b = (const float*)d_in[9];
    const float* fc_w   = (const float*)d_in[10];
    const float* fc_b   = (const float*)d_in[11];
    const float* lin2_w = (const float*)d_in[12];
    const float* lin2_b = (const float*)d_in[13];
    float* out = (float*)d_out;

    float *p_out0, *p_aggA, *p_aggB, *p_deg, *p_sums, *p_cnt;
    int *p_cntn;
    uint4* p_h;
    cudaGetSymbolAddress((void**)&p_out0, g_out0);
    cudaGetSymbolAddress((void**)&p_h,    g_hh);
    cudaGetSymbolAddress((void**)&p_aggA, g_aggA);
    cudaGetSymbolAddress((void**)&p_aggB, g_aggB);
    cudaGetSymbolAddress((void**)&p_deg,  g_deg);
    cudaGetSymbolAddress((void**)&p_sums, g_sums);
    cudaGetSymbolAddress((void**)&p_cnt,  g_cnt);
    cudaGetSymbolAddress((void**)&p_cntn, g_cntn);

    cudaMemsetAsync(p_deg, 0, NN * sizeof(float));
    cudaMemsetAsync(p_cntn, 0, NN * sizeof(int));
    cudaMemsetAsync(p_sums, 0, GG * D * sizeof(float));
    cudaMemsetAsync(p_cnt, 0, GG * sizeof(float));

    detect_kernel<<<1, 32>>>((const int*)ei, (const int*)batch);

    // fused lin0 GEMM + degree histogram (overlapped)
    const int GB = (NN + 127) / 128;           // 782 gemm blocks
    const int DB = (EE + 255) / 256;           // 6250 deg blocks
    fused_lin0_deg<<<GB + DB, 256>>>(x, lin0_w, lin0_b, p_out0, ei, ew, GB);

    scan1_kernel<<<SCAN_NB, SCAN_T>>>();
    scan2_kernel<<<1, 256>>>();
    scatter_kernel<<<(EE + 255) / 256, 256>>>(ei, ew);

    float* bufs[2] = {p_aggA, p_aggB};
    const float* Ain = p_out0;
    const int AGB = (NN * 32 + 255) / 256;
    const int TGB = (NN + 127) / 128;
    for (int i = 0; i < 4; i++) {
        gemm_tf32x3<<<TGB, 256>>>(Ain, conv_w + i * D * D, (unsigned*)p_h, NN);
        if (i < 3) {
            float* agg = bufs[i & 1];
            agg_half<<<AGB, 256>>>(p_h, conv_b + i * D, agg);
            Ain = agg;
        } else {
            agg_pool<<<AGB, 256>>>(p_h, conv_b + i * D, batch);
        }
    }

    tail_kernel<<<GG, 64>>>(lin1_w, lin1_b, fc_w, fc_b, lin2_w, lin2_b, out);
}

// round 7
// speedup vs baseline: 1.1453x; 1.1453x over previous
#include <cuda_runtime.h>
#include <cuda_fp16.h>

#define NN 100000
#define EE 1600000
#define FIN 100
#define D 64
#define GG 500
#define SCAN_T 512
#define SCAN_NB ((NN + SCAN_T - 1) / SCAN_T)

// ---------------- scratch (device globals; no allocs allowed) ----------------
__device__ float g_deg[NN];
__device__ int   g_cntn[NN];
__device__ int   g_ptr[NN + 1];
__device__ int   g_partials[SCAN_NB];
__device__ int2  g_csr[EE];        // packed {row, norm_bits}
__device__ float g_out0[NN * D];
__device__ uint4 g_hh[NN * 8];     // h in fp16: 64 halves = 8 uint4 per row
__device__ float g_aggA[NN * D];
__device__ float g_aggB[NN * D];
__device__ float g_sums[GG * D];
__device__ float g_cnt[GG];
__device__ int g_is64_edge;
__device__ int g_is64_batch;

__device__ __forceinline__ int load_idx(const void* p, long long i, int is64) {
    return is64 ? (int)((const long long*)p)[i] : ((const int*)p)[i];
}

// ptr fixup inlined (scan3 eliminated): final ptr(n) = g_ptr[n] + partials[n>>9]
__device__ __forceinline__ int ptr_of(int n) {
    return (n == NN) ? EE : g_ptr[n] + g_partials[n >> 9];
}

// Detect int64 vs int32 index arrays (odd 32-bit words all zero => int64).
__global__ void detect_kernel(const int* ei, const int* bat) {
    int i = threadIdx.x;  // 32 threads
    int nz_e = 0, nz_b = 0;
    for (int j = i; j < 128; j += 32) {
        int w = 1 + 700 * j;  // always odd, < NN words
        nz_e |= (ei[w] != 0);
        nz_b |= (bat[w] != 0);
    }
    unsigned be = __ballot_sync(0xffffffffu, nz_e);
    unsigned bb = __ballot_sync(0xffffffffu, nz_b);
    if (i == 0) {
        g_is64_edge = (be == 0);
        g_is64_batch = (bb == 0);
    }
}

// ---------------- fused: lin0 GEMM (fp32) + degree/count histogram -----------
#define K0 FIN
#define KB0 20
#define APAD 132
__global__ void fused_lin0_deg(const float* __restrict__ A, const float* __restrict__ W,
                               const float* __restrict__ biasC, float* __restrict__ C,
                               const void* ei, const float* __restrict__ ew,
                               int gemm_blocks) {
    __shared__ float Ws[K0 * D];
    __shared__ float As[KB0 * APAD];
    int tid = threadIdx.x;

    if (blockIdx.x >= gemm_blocks) {
        int e = (blockIdx.x - gemm_blocks) * 256 + tid;
        if (e < EE) {
            int c = load_idx(ei, (long long)EE + e, g_is64_edge);
            atomicAdd(&g_deg[c], ew[e]);
            atomicAdd(&g_cntn[c], 1);
        }
        return;
    }

    int row0 = blockIdx.x * 128;
    for (int i = tid; i < K0 * D; i += 256) Ws[i] = W[i];
    int tx = tid & 15, ty = tid >> 4;
    float acc[8][4] = {};

    for (int kb = 0; kb < K0; kb += KB0) {
        __syncthreads();
        for (int i = tid; i < 128 * KB0; i += 256) {
            int rr = i / KB0, kk = i - rr * KB0;
            int r = row0 + rr;
            As[kk * APAD + rr] = (r < NN) ? A[(long long)r * K0 + kb + kk] : 0.f;
        }
        __syncthreads();
#pragma unroll
        for (int k = 0; k < KB0; k++) {
            float4 a0 = *(const float4*)&As[k * APAD + ty * 8];
            float4 a1 = *(const float4*)&As[k * APAD + ty * 8 + 4];
            float4 wv = *(const float4*)&Ws[(kb + k) * D + tx * 4];
            float av[8] = {a0.x, a0.y, a0.z, a0.w, a1.x, a1.y, a1.z, a1.w};
#pragma unroll
            for (int i2 = 0; i2 < 8; i2++) {
                acc[i2][0] += av[i2] * wv.x;
                acc[i2][1] += av[i2] * wv.y;
                acc[i2][2] += av[i2] * wv.z;
                acc[i2][3] += av[i2] * wv.w;
            }
        }
    }
    int c0 = tx * 4;
    float4 bc = *(const float4*)&biasC[c0];
#pragma unroll
    for (int i2 = 0; i2 < 8; i2++) {
        int r = row0 + ty * 8 + i2;
        if (r >= NN) break;
        float4 v = make_float4(fmaxf(acc[i2][0] + bc.x, 0.f), fmaxf(acc[i2][1] + bc.y, 0.f),
                               fmaxf(acc[i2][2] + bc.z, 0.f), fmaxf(acc[i2][3] + bc.w, 0.f));
        *(float4*)&C[(long long)r * D + c0] = v;
    }
}

// ---------------- two-level exclusive scan over g_cntn -> g_ptr --------------
__global__ void scan1_kernel() {
    __shared__ int sh[SCAN_T];
    int tid = threadIdx.x;
    int i = blockIdx.x * SCAN_T + tid;
    int v = (i < NN) ? g_cntn[i] : 0;
    sh[tid] = v;
    __syncthreads();
    for (int off = 1; off < SCAN_T; off <<= 1) {
        int t = (tid >= off) ? sh[tid - off] : 0;
        __syncthreads();
        sh[tid] += t;
        __syncthreads();
    }
    if (i < NN) g_ptr[i] = sh[tid] - v;  // exclusive (local)
    if (tid == SCAN_T - 1) g_partials[blockIdx.x] = sh[tid];
}

__global__ void scan2_kernel() {  // 1 block of 256 (SCAN_NB=196 < 256)
    __shared__ int sh[256];
    int tid = threadIdx.x;
    int v = (tid < SCAN_NB) ? g_partials[tid] : 0;
    sh[tid] = v;
    __syncthreads();
    for (int off = 1; off < 256; off <<= 1) {
        int t = (tid >= off) ? sh[tid - off] : 0;
        __syncthreads();
        sh[tid] += t;
        __syncthreads();
    }
    if (tid < SCAN_NB) g_partials[tid] = sh[tid] - v;  // exclusive
}

// ---------------- SIMT fp32 conv GEMM (fp16 out) + optional fused scatter ----
// 128-row x 64-col tile, 256 threads, 8x4 per thread. h out as fp16 (uint2/thread).
// DO_SCATTER: blocks past gemm_blocks build the packed CSR (latency-bound,
// overlaps the FMA-bound GEMM).
template <bool DO_SCATTER>
__global__ void gemm_conv(const float* __restrict__ A, const float* __restrict__ W,
                          unsigned* __restrict__ hout, int nrows,
                          const void* ei, const float* __restrict__ ew,
                          int gemm_blocks) {
    __shared__ float Ws[D * D];
    __shared__ float As[32 * APAD];

    int tid = threadIdx.x;
    if (DO_SCATTER && blockIdx.x >= gemm_blocks) {
        int e = (blockIdx.x - gemm_blocks) * 256 + tid;
        if (e < EE) {
            int is64 = g_is64_edge;
            int r = load_idx(ei, e, is64);
            int c = load_idx(ei, (long long)EE + e, is64);
            float dr = g_deg[r], dc = g_deg[c];
            float ir = dr > 0.f ? rsqrtf(dr) : 0.f;
            float ic = dc > 0.f ? rsqrtf(dc) : 0.f;
            int old = atomicSub(&g_cntn[c], 1);
            int p = ptr_of(c) + old - 1;
            g_csr[p] = make_int2(r, __float_as_int(ir * ew[e] * ic));
        }
        return;
    }

    int row0 = blockIdx.x * 128;
    for (int i = tid; i < D * D; i += 256) Ws[i] = W[i];
    int tx = tid & 15, ty = tid >> 4;
    float acc[8][4] = {};

    for (int kb = 0; kb < D; kb += 32) {
        __syncthreads();
        for (int i = tid; i < 128 * 32; i += 256) {
            int rr = i >> 5, kk = i & 31;
            int r = row0 + rr;
            As[kk * APAD + rr] = (r < nrows) ? A[(long long)r * D + kb + kk] : 0.f;
        }
        __syncthreads();
#pragma unroll
        for (int k = 0; k < 32; k++) {
            float4 a0 = *(const float4*)&As[k * APAD + ty * 8];
            float4 a1 = *(const float4*)&As[k * APAD + ty * 8 + 4];
            float4 wv = *(const float4*)&Ws[(kb + k) * D + tx * 4];
            float av[8] = {a0.x, a0.y, a0.z, a0.w, a1.x, a1.y, a1.z, a1.w};
#pragma unroll
            for (int i2 = 0; i2 < 8; i2++) {
                acc[i2][0] += av[i2] * wv.x;
                acc[i2][1] += av[i2] * wv.y;
                acc[i2][2] += av[i2] * wv.z;
                acc[i2][3] += av[i2] * wv.w;
            }
        }
    }

#pragma unroll
    for (int i2 = 0; i2 < 8; i2++) {
        int r = row0 + ty * 8 + i2;
        if (r >= nrows) break;
        __half2 ha = __floats2half2_rn(acc[i2][0], acc[i2][1]);
        __half2 hb = __floats2half2_rn(acc[i2][2], acc[i2][3]);
        uint2 u;
        u.x = *(unsigned*)&ha;
        u.y = *(unsigned*)&hb;
        ((uint2*)hout)[(long long)r * 16 + tx] = u;
    }
}

// ---------------- CSR aggregation (fp16 gather, packed csr) ------------------
__device__ __forceinline__ void agg_core(int node, const uint4* __restrict__ h,
                                         int q, int p, float acc[8]) {
    int s = ptr_of(node), e = ptr_of(node + 1);
    for (int i = s + q; i < e; i += 4) {
        int2 ed = g_csr[i];
        float nv = __int_as_float(ed.y);
        uint4 u = h[ed.x * 8 + p];
        __half2* hh = (__half2*)&u;
#pragma unroll
        for (int c = 0; c < 4; c++) {
            float2 f = __half22float2(hh[c]);
            acc[2 * c]     += f.x * nv;
            acc[2 * c + 1] += f.y * nv;
        }
    }
#pragma unroll
    for (int c = 0; c < 8; c++) {
        acc[c] += __shfl_xor_sync(0xffffffffu, acc[c], 8);
        acc[c] += __shfl_xor_sync(0xffffffffu, acc[c], 16);
    }
}

__global__ void agg_half(const uint4* __restrict__ h,
                         const float* __restrict__ bias, float* __restrict__ outp) {
    int node = (blockIdx.x * blockDim.x + threadIdx.x) >> 5;
    if (node >= NN) return;
    int lane = threadIdx.x & 31;
    int q = lane >> 3, p = lane & 7;
    float acc[8] = {};
    agg_core(node, h, q, p, acc);
    if (q == 0) {
        float4 b0 = *(const float4*)&bias[8 * p];
        float4 b1 = *(const float4*)&bias[8 * p + 4];
        float4 o0 = make_float4(fmaxf(acc[0] + b0.x, 0.f), fmaxf(acc[1] + b0.y, 0.f),
                                fmaxf(acc[2] + b0.z, 0.f), fmaxf(acc[3] + b0.w, 0.f));
        float4 o1 = make_float4(fmaxf(acc[4] + b1.x, 0.f), fmaxf(acc[5] + b1.y, 0.f),
                                fmaxf(acc[6] + b1.z, 0.f), fmaxf(acc[7] + b1.w, 0.f));
        float* row = outp + (long long)node * D + 8 * p;
        *(float4*)row = o0;
        *(float4*)(row + 4) = o1;
    }
}

__device__ __forceinline__ void red_add_v4(float4* addr, float4 v) {
    asm volatile("red.global.add.v4.f32 [%0], {%1,%2,%3,%4};"
                 :: "l"(addr), "f"(v.x), "f"(v.y), "f"(v.z), "f"(v.w)
                 : "memory");
}

// Last layer: aggregate + bias + relu + mean-pool accumulate.
__global__ void agg_pool(const uint4* __restrict__ h,
                         const float* __restrict__ bias, const void* batch) {
    int node = (blockIdx.x * blockDim.x + threadIdx.x) >> 5;
    if (node >= NN) return;
    int lane = threadIdx.x & 31;
    int q = lane >> 3, p = lane & 7;
    float acc[8] = {};
    agg_core(node, h, q, p, acc);
    if (q == 0) {
        int g = load_idx(batch, node, g_is64_batch);
        float4 b0 = *(const float4*)&bias[8 * p];
        float4 b1 = *(const float4*)&bias[8 * p + 4];
        float4 o0 = make_float4(fmaxf(acc[0] + b0.x, 0.f), fmaxf(acc[1] + b0.y, 0.f),
                                fmaxf(acc[2] + b0.z, 0.f), fmaxf(acc[3] + b0.w, 0.f));
        float4 o1 = make_float4(fmaxf(acc[4] + b1.x, 0.f), fmaxf(acc[5] + b1.y, 0.f),
                                fmaxf(acc[6] + b1.z, 0.f), fmaxf(acc[7] + b1.w, 0.f));
        float* row = g_sums + g * D + 8 * p;
        red_add_v4((float4*)row, o0);
        red_add_v4((float4*)(row + 4), o1);
        if (p == 0) atomicAdd(&g_cnt[g], 1.0f);
    }
}

// ---------------- fused MLP tail: lin1 -> fc0 -> fc1 -> lin2 ----------------
__global__ void tail_kernel(const float* __restrict__ W1, const float* __restrict__ b1,
                            const float* __restrict__ fcw, const float* __restrict__ fcb,
                            const float* __restrict__ w2, const float* __restrict__ b2,
                            float* __restrict__ out) {
    int g = blockIdx.x, tid = threadIdx.x;  // 64 threads
    __shared__ float buf[2][64];
    __shared__ float red[64];

    buf[0][tid] = g_sums[g * D + tid] / fmaxf(g_cnt[g], 1.f);
    __syncthreads();
    {
        float acc = 0.f;
#pragma unroll
        for (int k = 0; k < 64; k++) acc += buf[0][k] * W1[k * D + tid];
        buf[1][tid] = fmaxf(acc + b1[tid], 0.f);
        __syncthreads();
    }
    int cur = 1;
    for (int L = 0; L < 2; L++) {
        const float* W = fcw + L * D * D;
        float acc = 0.f;
#pragma unroll
        for (int k = 0; k < 64; k++) acc += buf[cur][k] * W[k * D + tid];
        __syncthreads();
        buf[cur ^ 1][tid] = fmaxf(acc + fcb[L * D + tid], 0.f);
        cur ^= 1;
        __syncthreads();
    }
    red[tid] = buf[cur][tid] * w2[tid];
    __syncthreads();
    if (tid < 32) {
        float s = red[tid] + red[tid + 32];
#pragma unroll
        for (int off = 16; off; off >>= 1) s += __shfl_down_sync(0xffffffffu, s, off);
        if (tid == 0) out[g] = s + b2[0];
    }
}

// ---------------- launch ----------------
extern "C" void kernel_launch(void* const* d_in, const int* in_sizes, int n_in,
                              void* d_out, int out_size) {
    const float* x      = (const float*)d_in[0];
    const void*  ei     = d_in[1];
    const float* ew     = (const float*)d_in[2];
    const void*  batch  = d_in[3];
    const float* lin0_w = (const float*)d_in[4];
    const float* lin0_b = (const float*)d_in[5];
    const float* conv_w = (const float*)d_in[6];
    const float* conv_b = (const float*)d_in[7];
    const float* lin1_w = (const float*)d_in[8];
    const float* lin1_b = (const float*)d_in[9];
    const float* fc_w   = (const float*)d_in[10];
    const float* fc_b   = (const float*)d_in[11];
    const float* lin2_w = (const float*)d_in[12];
    const float* lin2_b = (const float*)d_in[13];
    float* out = (float*)d_out;

    float *p_out0, *p_aggA, *p_aggB, *p_deg, *p_sums, *p_cnt;
    int *p_cntn;
    uint4* p_h;
    cudaGetSymbolAddress((void**)&p_out0, g_out0);
    cudaGetSymbolAddress((void**)&p_h,    g_hh);
    cudaGetSymbolAddress((void**)&p_aggA, g_aggA);
    cudaGetSymbolAddress((void**)&p_aggB, g_aggB);
    cudaGetSymbolAddress((void**)&p_deg,  g_deg);
    cudaGetSymbolAddress((void**)&p_sums, g_sums);
    cudaGetSymbolAddress((void**)&p_cnt,  g_cnt);
    cudaGetSymbolAddress((void**)&p_cntn, g_cntn);

    cudaMemsetAsync(p_deg, 0, NN * sizeof(float));
    cudaMemsetAsync(p_cntn, 0, NN * sizeof(int));
    cudaMemsetAsync(p_sums, 0, GG * D * sizeof(float));
    cudaMemsetAsync(p_cnt, 0, GG * sizeof(float));

    detect_kernel<<<1, 32>>>((const int*)ei, (const int*)batch);

    // fused lin0 GEMM + degree histogram (overlapped)
    const int GB = (NN + 127) / 128;           // 782 gemm blocks
    const int DB = (EE + 255) / 256;           // 6250 edge blocks
    fused_lin0_deg<<<GB + DB, 256>>>(x, lin0_w, lin0_b, p_out0, ei, ew, GB);

    scan1_kernel<<<SCAN_NB, SCAN_T>>>();
    scan2_kernel<<<1, 256>>>();

    float* bufs[2] = {p_aggA, p_aggB};
    const float* Ain = p_out0;
    const int AGB = (NN * 32 + 255) / 256;
    for (int i = 0; i < 4; i++) {
        if (i == 0) {
            // conv-0 GEMM fused with CSR scatter (overlapped)
            gemm_conv<true><<<GB + DB, 256>>>(Ain, conv_w, (unsigned*)p_h, NN, ei, ew, GB);
        } else {
            gemm_conv<false><<<GB, 256>>>(Ain, conv_w + i * D * D, (unsigned*)p_h, NN,
                                          ei, ew, GB);
        }
        if (i < 3) {
            float* agg = bufs[i & 1];
            agg_half<<<AGB, 256>>>(p_h, conv_b + i * D, agg);
            Ain = agg;
        } else {
            agg_pool<<<AGB, 256>>>(p_h, conv_b + i * D, batch);
        }
    }

    tail_kernel<<<GG, 64>>>(lin1_w, lin1_b, fc_w, fc_b, lin2_w, lin2_b, out);
}